// round 3
// baseline (speedup 1.0000x reference)
#include <cuda_runtime.h>

#define N_NODES 10000
#define N_EDGES 640000

#define BE 64          // edges per block tile
#define TE 256         // edge kernel threads (8 warps)
#define TN 512         // node kernel threads
#define ES 66          // col-major activation tile stride (64 edges + 2 pad)

typedef unsigned long long u64;

// Scratch (device globals: no allocation allowed)
__device__ float g_hagg[N_NODES * 128];
__device__ float g_cagg[N_NODES * 3];
__device__ float g_cnt[N_NODES];

__device__ __forceinline__ float silu_f(float x) {
    return x / (1.0f + __expf(-x));
}

// ---------------- packed f32x2 primitives ----------------
__device__ __forceinline__ void fma2(u64 &d, u64 a, u64 b) {
    asm("fma.rn.f32x2 %0, %1, %2, %0;" : "+l"(d) : "l"(a), "l"(b));
}
__device__ __forceinline__ u64 dup2(float w) {
    u64 r; asm("mov.b64 %0, {%1, %1};" : "=l"(r) : "f"(w)); return r;
}
__device__ __forceinline__ void unpack2(u64 p, float &lo, float &hi) {
    asm("mov.b64 {%0, %1}, %2;" : "=f"(lo), "=f"(hi) : "l"(p));
}

// One k-step: acc[c][p] += a_pair[p] * (w_c, w_c)
// aRow: col-major activation row (this warp's 8 edges, 8B-aligned)
// wRow: 128 floats (one k row of W); lane owns cols {tx, tx+32, tx+64, tx+96}
__device__ __forceinline__ void kstep(const float* __restrict__ aRow,
                                      const float* __restrict__ wRow,
                                      int tx, u64 acc[4][4])
{
    u64 a0 = *(const u64*)(aRow + 0);
    u64 a1 = *(const u64*)(aRow + 2);
    u64 a2 = *(const u64*)(aRow + 4);
    u64 a3 = *(const u64*)(aRow + 6);
#pragma unroll
    for (int c = 0; c < 4; c++) {
        u64 w = dup2(wRow[tx + 32 * c]);
        fma2(acc[c][0], a0, w);
        fma2(acc[c][1], a1, w);
        fma2(acc[c][2], a2, w);
        fma2(acc[c][3], a3, w);
    }
}

// Epilogue: bias + (optional) silu, store col-major [c][e] (stride ES)
__device__ __forceinline__ void epilogue(u64 acc[4][4],
                                         const float* __restrict__ bias,
                                         float* __restrict__ sOut,
                                         int e0, int tx, bool do_silu)
{
#pragma unroll
    for (int c = 0; c < 4; c++) {
        int cg = tx + 32 * c;
        float b = bias[cg];
#pragma unroll
        for (int p = 0; p < 4; p++) {
            float lo, hi; unpack2(acc[c][p], lo, hi);
            lo += b; hi += b;
            if (do_silu) { lo = silu_f(lo); hi = silu_f(hi); }
            *(float2*)&sOut[cg * ES + e0 + 2 * p] = make_float2(lo, hi);
        }
    }
}

// GEMM, K=128, weights fully preloaded in SMEM [128][128]
__device__ __forceinline__ void gemm_pre128(const float* __restrict__ sIn,
                                            const float* __restrict__ sW,
                                            const float* __restrict__ bias,
                                            float* __restrict__ sOut,
                                            int e0, int tx, bool do_silu)
{
    u64 acc[4][4];
#pragma unroll
    for (int c = 0; c < 4; c++)
#pragma unroll
        for (int p = 0; p < 4; p++) acc[c][p] = 0ull;

#pragma unroll 8
    for (int k = 0; k < 128; k++)
        kstep(sIn + k * ES + e0, sW + k * 128, tx, acc);

    epilogue(acc, bias, sOut, e0, tx, do_silu);
}

// GEMM1, K=257, weights streamed L2->SMEM in 16-row chunks, double-buffered
__device__ __forceinline__ void gemm1_257(const float* __restrict__ sIn,
                                          const float* __restrict__ Wg,
                                          const float* __restrict__ bias,
                                          float* __restrict__ sOut,
                                          float* __restrict__ s_w,
                                          int e0, int tx, int tid, bool do_silu)
{
    u64 acc[4][4];
#pragma unroll
    for (int c = 0; c < 4; c++)
#pragma unroll
        for (int p = 0; p < 4; p++) acc[c][p] = 0ull;

    // chunk 0 -> buffer 0
    {
        const float* p = Wg + tid * 8;
        float4 v0 = *(const float4*)p;
        float4 v1 = *(const float4*)(p + 4);
        *(float4*)(s_w + tid * 8)     = v0;
        *(float4*)(s_w + tid * 8 + 4) = v1;
    }
    __syncthreads();   // also covers the gather into sIn

    int cb = 0;
#pragma unroll 1
    for (int ch = 0; ch < 16; ch++) {
        float4 n0, n1; float tv = 0.0f;
        if (ch < 15) {
            const float* p = Wg + (ch + 1) * 2048 + tid * 8;
            n0 = *(const float4*)p;
            n1 = *(const float4*)(p + 4);
        } else if (tid < 128) {
            tv = Wg[256 * 128 + tid];   // tail row k=256
        }

        const float* sW = s_w + cb * 2048;
        const float* aB = sIn + ch * 16 * ES + e0;
#pragma unroll
        for (int kk = 0; kk < 16; kk++)
            kstep(aB + kk * ES, sW + kk * 128, tx, acc);

        float* dst = s_w + (cb ^ 1) * 2048;
        if (ch < 15) {
            *(float4*)(dst + tid * 8)     = n0;
            *(float4*)(dst + tid * 8 + 4) = n1;
        } else if (tid < 128) {
            dst[tid] = tv;
        }
        __syncthreads();
        cb ^= 1;
    }
    // tail k = 256
    kstep(sIn + 256 * ES + e0, s_w + cb * 2048, tx, acc);

    epilogue(acc, bias, sOut, e0, tx, do_silu);
}

// ---------------- SMEM layout (edge kernel, floats) ----------------
// s_a    : 260*66 = 17160   (col-major input tile, K rows x 64 edges)
// s_w    : 2*2048 = 4096    (double-buffered W chunk for GEMM1)
// s_hid  : 128*66 = 8448
// s_ef   : 128*66 = 8448
// extras : diff 256, part 256, scalar 64, wc2 128, row/col 128 ints
#define SMEM_EDGE_FLOATS (17160 + 4096 + 8448 + 8448 + 256 + 256 + 64 + 128 + 128)
#define SMEM_EDGE_BYTES  (SMEM_EDGE_FLOATS * 4)

__global__ void __launch_bounds__(TE, 1)
zero_kernel()
{
    int i = blockIdx.x * blockDim.x + threadIdx.x;
    int st = gridDim.x * blockDim.x;
    for (int k = i; k < N_NODES * 128; k += st) g_hagg[k] = 0.0f;
    for (int k = i; k < N_NODES * 3;   k += st) g_cagg[k] = 0.0f;
    for (int k = i; k < N_NODES;       k += st) g_cnt[k]  = 0.0f;
}

__global__ void __launch_bounds__(TE, 1)
edge_kernel(const float* __restrict__ h, const float* __restrict__ y,
            const int* __restrict__ ei,
            const float* __restrict__ We1, const float* __restrict__ be1,
            const float* __restrict__ We2, const float* __restrict__ be2,
            const float* __restrict__ Wc1, const float* __restrict__ bc1,
            const float* __restrict__ Wc2)
{
    extern __shared__ float sm[];
    float* s_a      = sm;                  // [260][66] col-major
    float* s_w      = s_a + 17160;         // 2 x [16][128]
    float* s_hid    = s_w + 4096;          // [128][66]
    float* s_ef     = s_hid + 8448;        // [128][66]
    float* s_diff   = s_ef + 8448;         // [64][4]
    float* s_part   = s_diff + 256;        // [4][64]
    float* s_scalar = s_part + 256;        // [64]
    float* s_wc2    = s_scalar + 64;       // [128]
    int*   s_row    = (int*)(s_wc2 + 128); // [64]
    int*   s_col    = s_row + 64;          // [64]
    float* s_wbig   = s_a;                 // alias: 16384 <= 17160 floats
    float* s_c1     = s_hid;               // alias: GEMM3 output over dead s_hid

    const int tid  = threadIdx.x;
    const int lane = tid & 31;
    const int wid  = tid >> 5;
    const int tx   = lane;
    const int e0   = wid * 8;              // this warp's 8 edges
    const int e0g  = blockIdx.x * BE;

    if (tid < 64) {
        int r = ei[e0g + tid];
        int c = ei[N_EDGES + e0g + tid];
        s_row[tid] = r;
        s_col[tid] = c;
        float dx = y[r * 3 + 0] - y[c * 3 + 0];
        float dy = y[r * 3 + 1] - y[c * 3 + 1];
        float dz = y[r * 3 + 2] - y[c * 3 + 2];
        s_diff[tid * 4 + 0] = dx;
        s_diff[tid * 4 + 1] = dy;
        s_diff[tid * 4 + 2] = dz;
        s_a[256 * ES + tid] = dx * dx + dy * dy + dz * dz;   // radial row
    }
    if (tid < 128) s_wc2[tid] = Wc2[tid];
    __syncthreads();

    // Gather h[row], h[col] -> s_a col-major: s_a[k][e]
    for (int t = wid; t < 2 * BE; t += 8) {
        int e = t >> 1, half = t & 1;
        int node = half ? s_col[e] : s_row[e];
        const float* hp = h + (size_t)node * 128;
#pragma unroll
        for (int j = 0; j < 4; j++) {
            float v = hp[lane + 32 * j];
            s_a[(half * 128 + lane + 32 * j) * ES + e] = v;
        }
    }
    // (gemm1's first __syncthreads covers the gather)

    gemm1_257(s_a, We1, be1, s_hid, s_w, e0, tx, tid, true);
    __syncthreads();                       // all s_a reads done

    // Preload We2 (64KB) over dead s_a
#pragma unroll
    for (int i = 0; i < 16; i++)
        *(float4*)(s_wbig + i * 1024 + tid * 4) =
            *(const float4*)(We2 + i * 1024 + tid * 4);
    __syncthreads();
    gemm_pre128(s_hid, s_wbig, be2, s_ef, e0, tx, true);
    __syncthreads();

    // Preload Wc1 over the same region
#pragma unroll
    for (int i = 0; i < 16; i++)
        *(float4*)(s_wbig + i * 1024 + tid * 4) =
            *(const float4*)(Wc1 + i * 1024 + tid * 4);
    __syncthreads();
    gemm_pre128(s_ef, s_wbig, bc1, s_c1, e0, tx, true);
    __syncthreads();

    // GEMV: scalar[e] = c1[:,e] . Wc2  (c1 col-major)
    {
        int e = tid & 63, q = tid >> 6;
        float s = 0.0f;
#pragma unroll 8
        for (int c = q * 32; c < q * 32 + 32; c++)
            s += s_c1[c * ES + e] * s_wc2[c];
        s_part[q * 64 + e] = s;
    }
    __syncthreads();

    // coord scatter + count
    if (tid < 64) {
        float s = s_part[tid] + s_part[64 + tid] + s_part[128 + tid] + s_part[192 + tid];
        int r = s_row[tid];
        atomicAdd(&g_cagg[r * 3 + 0], s_diff[tid * 4 + 0] * s);
        atomicAdd(&g_cagg[r * 3 + 1], s_diff[tid * 4 + 1] * s);
        atomicAdd(&g_cagg[r * 3 + 2], s_diff[tid * 4 + 2] * s);
        atomicAdd(&g_cnt[r], 1.0f);
    }

    // edge_feat scatter (s_ef col-major: read [j][e], lanes sweep e -> conflict-free)
    for (int idx = tid; idx < BE * 128; idx += TE) {
        int e = idx & 63, j = idx >> 6;
        atomicAdd(&g_hagg[(size_t)s_row[e] * 128 + j], s_ef[j * ES + e]);
    }
}

// ================= node kernel (unchanged scalar path, ~1.5% of time) =========
#define IN_STRIDE 264
#define HID_STRIDE 132

template<int K, bool SILU>
__device__ __forceinline__ void gemm_tile(
    const float* __restrict__ sIn, int inStride,
    const float* __restrict__ W, const float* __restrict__ bias,
    float* __restrict__ sOut, int outStride,
    float* __restrict__ s_w)
{
    const int tx = threadIdx.x & 31;
    const int ty = threadIdx.x >> 5;   // 0..15
    const int r0 = ty * 4;

    float acc[4][4];
#pragma unroll
    for (int i = 0; i < 4; i++)
#pragma unroll
        for (int c = 0; c < 4; c++) acc[i][c] = 0.0f;

    constexpr int KFULL = (K / 16) * 16;

    for (int kc = 0; kc < KFULL; kc += 16) {
        __syncthreads();
        {
            int t = threadIdx.x;
            int r = t >> 5, c = t & 31;
            ((float4*)s_w)[r * 33 + c] =
                *((const float4*)(W + (size_t)(kc + r) * 128) + c);
        }
        __syncthreads();
#pragma unroll
        for (int kk = 0; kk < 16; kk += 4) {
            float4 av[4];
#pragma unroll
            for (int i = 0; i < 4; i++)
                av[i] = *(const float4*)&sIn[(r0 + i) * inStride + kc + kk];
#pragma unroll
            for (int q = 0; q < 4; q++) {
                float4 w = ((const float4*)s_w)[(kk + q) * 33 + tx];
#pragma unroll
                for (int i = 0; i < 4; i++) {
                    float a = (q == 0) ? av[i].x : (q == 1) ? av[i].y
                              : (q == 2) ? av[i].z : av[i].w;
                    acc[i][0] = fmaf(a, w.x, acc[i][0]);
                    acc[i][1] = fmaf(a, w.y, acc[i][1]);
                    acc[i][2] = fmaf(a, w.z, acc[i][2]);
                    acc[i][3] = fmaf(a, w.w, acc[i][3]);
                }
            }
        }
    }

    float4 b = *((const float4*)bias + tx);
#pragma unroll
    for (int i = 0; i < 4; i++) {
        float4 v;
        v.x = acc[i][0] + b.x;
        v.y = acc[i][1] + b.y;
        v.z = acc[i][2] + b.z;
        v.w = acc[i][3] + b.w;
        if (SILU) {
            v.x = silu_f(v.x); v.y = silu_f(v.y);
            v.z = silu_f(v.z); v.w = silu_f(v.w);
        }
        *(float4*)&sOut[(r0 + i) * outStride + tx * 4] = v;
    }
}

#define SM_IN    (BE * IN_STRIDE)
#define SM_W     (16 * 33 * 4)
#define SM_HID   (BE * HID_STRIDE)
#define SMEM_NODE_FLOATS (SM_IN + SM_W + SM_HID)
#define SMEM_NODE_BYTES  (SMEM_NODE_FLOATS * 4)

__global__ void __launch_bounds__(TN, 1)
node_kernel(const float* __restrict__ h, const float* __restrict__ y,
            const float* __restrict__ Wn1, const float* __restrict__ bn1,
            const float* __restrict__ Wn2, const float* __restrict__ bn2,
            float* __restrict__ out_h, float* __restrict__ out_y)
{
    extern __shared__ float sm[];
    float* s_in  = sm;
    float* s_w   = s_in + SM_IN;
    float* s_hid = s_w + SM_W;

    const int tid  = threadIdx.x;
    const int lane = tid & 31;
    const int wid  = tid >> 5;
    const int n0   = blockIdx.x * BE;

    for (int t = wid; t < 2 * BE; t += 16) {
        int e = t >> 1, half = t & 1;
        int n = n0 + e;
        float4 v = make_float4(0.f, 0.f, 0.f, 0.f);
        if (n < N_NODES) {
            const float* src = half ? (g_hagg + (size_t)n * 128)
                                    : (h + (size_t)n * 128);
            v = *((const float4*)src + lane);
        }
        *(float4*)&s_in[e * IN_STRIDE + half * 128 + lane * 4] = v;
    }

    gemm_tile<256, true>(s_in, IN_STRIDE, Wn1, bn1, s_hid, HID_STRIDE, s_w);
    gemm_tile<128, false>(s_hid, HID_STRIDE, Wn2, bn2, s_in + 128, IN_STRIDE, s_w);
    __syncthreads();

    for (int idx = tid; idx < BE * 128; idx += TN) {
        int e = idx >> 7, j = idx & 127;
        int n = n0 + e;
        if (n < N_NODES)
            out_h[(size_t)n * 128 + j] = s_in[e * IN_STRIDE + j]
                                       + s_in[e * IN_STRIDE + 128 + j];
    }
    if (tid < BE) {
        int n = n0 + tid;
        if (n < N_NODES) {
            float c = g_cnt[n];
            c = (c < 1.0f) ? 1.0f : c;
            out_y[n * 3 + 0] = y[n * 3 + 0] + g_cagg[n * 3 + 0] / c;
            out_y[n * 3 + 1] = y[n * 3 + 1] + g_cagg[n * 3 + 1] / c;
            out_y[n * 3 + 2] = y[n * 3 + 2] + g_cagg[n * 3 + 2] / c;
        }
    }
}

extern "C" void kernel_launch(void* const* d_in, const int* in_sizes, int n_in,
                              void* d_out, int out_size)
{
    const float* h   = (const float*)d_in[0];
    const float* y   = (const float*)d_in[1];
    const int*   ei  = (const int*)d_in[2];
    const float* We1 = (const float*)d_in[3];
    const float* be1 = (const float*)d_in[4];
    const float* We2 = (const float*)d_in[5];
    const float* be2 = (const float*)d_in[6];
    const float* Wc1 = (const float*)d_in[7];
    const float* bc1 = (const float*)d_in[8];
    const float* Wc2 = (const float*)d_in[9];
    const float* Wn1 = (const float*)d_in[10];
    const float* bn1 = (const float*)d_in[11];
    const float* Wn2 = (const float*)d_in[12];
    const float* bn2 = (const float*)d_in[13];

    float* out_h = (float*)d_out;
    float* out_y = out_h + (size_t)N_NODES * 128;

    cudaFuncSetAttribute(edge_kernel, cudaFuncAttributeMaxDynamicSharedMemorySize,
                         SMEM_EDGE_BYTES);
    cudaFuncSetAttribute(node_kernel, cudaFuncAttributeMaxDynamicSharedMemorySize,
                         SMEM_NODE_BYTES);

    zero_kernel<<<512, TE>>>();

    edge_kernel<<<N_EDGES / BE, TE, SMEM_EDGE_BYTES>>>(
        h, y, ei, We1, be1, We2, be2, Wc1, bc1, Wc2);

    node_kernel<<<(N_NODES + BE - 1) / BE, TN, SMEM_NODE_BYTES>>>(
        h, y, Wn1, bn1, Wn2, bn2, out_h, out_y);
}

// round 5
// speedup vs baseline: 1.8181x; 1.8181x over previous
#include <cuda_runtime.h>
#include <cstdint>

#define N_NODES 10000
#define N_EDGES 640000
#define TE 256
#define TN 512

typedef uint32_t u32;

// ---------------- device scratch ----------------
__device__ float g_hagg[N_NODES * 128];
__device__ float g_cagg[N_NODES * 3];
__device__ float g_cnt[N_NODES];
// B fragments: [chunk][ntile=16][lane=32] float4(hi_b0, hi_b1, lo_b0, lo_b1)
__device__ float4 g_Bf1[33 * 512];
__device__ float4 g_Bf2[16 * 512];
__device__ float4 g_Bf3[16 * 512];

__device__ __forceinline__ float silu_f(float x) { return x / (1.0f + __expf(-x)); }
__device__ __forceinline__ u32 cvt_tf32(float x) {
    u32 u; asm("cvt.rna.tf32.f32 %0, %1;" : "=r"(u) : "f"(x)); return u;
}

#define MMA_TF32(d, a0, a1, a2, a3, b0, b1)                                \
    asm volatile(                                                          \
        "mma.sync.aligned.m16n8k8.row.col.f32.tf32.tf32.f32 "              \
        "{%0,%1,%2,%3},{%4,%5,%6,%7},{%8,%9},{%0,%1,%2,%3};"               \
        : "+f"((d)[0]), "+f"((d)[1]), "+f"((d)[2]), "+f"((d)[3])           \
        : "r"(a0), "r"(a1), "r"(a2), "r"(a3), "r"(b0), "r"(b1))

// ---------------- prep: weights -> tf32 hi/lo fragments ----------------
__global__ void prep_kernel(const float* __restrict__ We1,
                            const float* __restrict__ We2,
                            const float* __restrict__ Wc1)
{
    int i = blockIdx.x * blockDim.x + threadIdx.x;
    const float* W; float4* dst; int K, idx;
    if (i < 33 * 512)            { W = We1; dst = g_Bf1; K = 257; idx = i; }
    else if (i < 49 * 512)       { W = We2; dst = g_Bf2; K = 128; idx = i - 33 * 512; }
    else if (i < 65 * 512)       { W = Wc1; dst = g_Bf3; K = 128; idx = i - 49 * 512; }
    else return;

    int c = idx >> 9, rem = idx & 511;
    int t = rem >> 5, l = rem & 31;
    int g = l >> 2, tig = l & 3;
    int n = t * 8 + g;
    int ka = c * 8 + tig, kb = ka + 4;
    float wa = (ka < K) ? W[ka * 128 + n] : 0.0f;
    float wb = (kb < K) ? W[kb * 128 + n] : 0.0f;
    u32 ha = cvt_tf32(wa), hb = cvt_tf32(wb);
    u32 la = cvt_tf32(wa - __uint_as_float(ha));
    u32 lb = cvt_tf32(wb - __uint_as_float(hb));
    dst[idx] = make_float4(__uint_as_float(ha), __uint_as_float(hb),
                           __uint_as_float(la), __uint_as_float(lb));
}

__global__ void zero_kernel()
{
    int i = blockIdx.x * blockDim.x + threadIdx.x;
    int st = gridDim.x * blockDim.x;
    for (int k = i; k < N_NODES * 128; k += st) g_hagg[k] = 0.0f;
    for (int k = i; k < N_NODES * 3;   k += st) g_cagg[k] = 0.0f;
    for (int k = i; k < N_NODES;       k += st) g_cnt[k]  = 0.0f;
}

// ---------------- mma GEMM: D[64][128] += act-tile @ W ----------------
// As row-major [64][SA]; Bf fragment array; acc[2 mtiles][4 ntiles][4]
template<int KC>
__device__ __forceinline__ void mma_gemm(const float* __restrict__ As, int SA,
                                         const float4* __restrict__ Bf,
                                         float acc[2][4][4],
                                         int m0, int ntb, int g, int tig, int lane)
{
    const float* r0 = As + (m0 + g) * SA;
    const float* r1 = r0 + 8 * SA;
    const float* r2 = r0 + 16 * SA;
    const float* r3 = r0 + 24 * SA;
    const float4* bp = Bf + ntb * 32 + lane;

    float  ar[2][8];
    float4 bf[2][4];
    {
        int k = tig;
        ar[0][0] = r0[k];   ar[0][1] = r1[k];   ar[0][2] = r0[k+4]; ar[0][3] = r1[k+4];
        ar[0][4] = r2[k];   ar[0][5] = r3[k];   ar[0][6] = r2[k+4]; ar[0][7] = r3[k+4];
        bf[0][0] = __ldg(bp +  0); bf[0][1] = __ldg(bp + 32);
        bf[0][2] = __ldg(bp + 64); bf[0][3] = __ldg(bp + 96);
    }
#pragma unroll 2
    for (int c = 0; c < KC; c++) {
        int cur = c & 1, nxt = cur ^ 1;
        if (c + 1 < KC) {
            int k = (c + 1) * 8 + tig;
            ar[nxt][0] = r0[k];   ar[nxt][1] = r1[k];
            ar[nxt][2] = r0[k+4]; ar[nxt][3] = r1[k+4];
            ar[nxt][4] = r2[k];   ar[nxt][5] = r3[k];
            ar[nxt][6] = r2[k+4]; ar[nxt][7] = r3[k+4];
            const float4* bq = bp + (size_t)(c + 1) * 512;
            bf[nxt][0] = __ldg(bq +  0); bf[nxt][1] = __ldg(bq + 32);
            bf[nxt][2] = __ldg(bq + 64); bf[nxt][3] = __ldg(bq + 96);
        }
        u32 ah[8], al[8];
#pragma unroll
        for (int j = 0; j < 8; j++) {
            ah[j] = cvt_tf32(ar[cur][j]);
            al[j] = cvt_tf32(ar[cur][j] - __uint_as_float(ah[j]));
        }
#pragma unroll
        for (int nt = 0; nt < 4; nt++) {
            u32 bh0 = __float_as_uint(bf[cur][nt].x);
            u32 bh1 = __float_as_uint(bf[cur][nt].y);
            u32 bl0 = __float_as_uint(bf[cur][nt].z);
            u32 bl1 = __float_as_uint(bf[cur][nt].w);
            MMA_TF32(acc[0][nt], ah[0], ah[1], ah[2], ah[3], bh0, bh1);
            MMA_TF32(acc[0][nt], al[0], al[1], al[2], al[3], bh0, bh1);
            MMA_TF32(acc[0][nt], ah[0], ah[1], ah[2], ah[3], bl0, bl1);
            MMA_TF32(acc[1][nt], ah[4], ah[5], ah[6], ah[7], bh0, bh1);
            MMA_TF32(acc[1][nt], al[4], al[5], al[6], al[7], bh0, bh1);
            MMA_TF32(acc[1][nt], ah[4], ah[5], ah[6], ah[7], bl0, bl1);
        }
    }
}

// ---------------- SMEM layout (floats) ----------------
#define SA1 268                       // As1 stride (conflict-free frag loads)
#define SAH 132                       // hid / ef stride
#define OFF_AS1  0                    // 64*268 = 17152  (ef aliases here later)
#define OFF_HID  17152                // 64*132 = 8448
#define OFF_MISC 25600
#define SMEM_EDGE_FLOATS (OFF_MISC + 512 + 192 + 256 + 128)
#define SMEM_EDGE_BYTES  (SMEM_EDGE_FLOATS * 4)

__global__ void __launch_bounds__(TE, 2)
edge_kernel(const float* __restrict__ h, const float* __restrict__ y,
            const int* __restrict__ ei,
            const float* __restrict__ be1, const float* __restrict__ be2,
            const float* __restrict__ bc1, const float* __restrict__ Wc2)
{
    extern __shared__ float sm[];
    float* As1   = sm + OFF_AS1;
    float* hid   = sm + OFF_HID;
    float* ef    = sm + OFF_AS1;             // alias over dead As1
    float* s_be1 = sm + OFF_MISC;
    float* s_be2 = s_be1 + 128;
    float* s_bc1 = s_be2 + 128;
    float* s_wc2 = s_bc1 + 128;
    float* s_diff = s_wc2 + 128;             // [64][3]
    float* s_part = s_diff + 192;            // [4][64]
    int*   s_row  = (int*)(s_part + 256);    // [64]
    int*   s_col  = s_row + 64;              // [64]

    const int tid  = threadIdx.x;
    const int lane = tid & 31;
    const int wid  = tid >> 5;
    const int g    = lane >> 2;
    const int tig  = lane & 3;
    const int mw   = wid >> 2;               // 0..1
    const int nw   = wid & 3;                // 0..3
    const int m0   = mw * 32;
    const int ntb  = nw * 4;
    const int e0g  = blockIdx.x * 64;

    // ---- stage: indices, diff/radial, biases ----
    if (tid < 64) {
        int r = ei[e0g + tid], c = ei[N_EDGES + e0g + tid];
        s_row[tid] = r; s_col[tid] = c;
        float dx = y[r*3+0]-y[c*3+0], dy = y[r*3+1]-y[c*3+1], dz = y[r*3+2]-y[c*3+2];
        s_diff[tid*3+0] = dx; s_diff[tid*3+1] = dy; s_diff[tid*3+2] = dz;
        float* row = As1 + tid * SA1;
        row[256] = dx*dx + dy*dy + dz*dz;
#pragma unroll
        for (int j = 257; j < 264; j++) row[j] = 0.0f;
    }
    if (tid < 128) {
        s_be1[tid] = be1[tid]; s_be2[tid] = be2[tid];
        s_bc1[tid] = bc1[tid]; s_wc2[tid] = Wc2[tid];
    }
    __syncthreads();   // s_row/s_col ready for gather

    // ---- gather h[row] | h[col] into As1 rows ----
    for (int t = wid; t < 128; t += 8) {
        int e = t >> 1, half = t & 1;
        int node = half ? s_col[e] : s_row[e];
        float4 v = *((const float4*)(h + (size_t)node * 128) + lane);
        *(float4*)&As1[e * SA1 + half * 128 + lane * 4] = v;
    }
    __syncthreads();

    float acc[2][4][4];
#define ZACC() do { _Pragma("unroll") for (int a_ = 0; a_ < 2; a_++) \
    _Pragma("unroll") for (int b_ = 0; b_ < 4; b_++) \
    _Pragma("unroll") for (int c_ = 0; c_ < 4; c_++) acc[a_][b_][c_] = 0.0f; } while (0)

    // ================= GEMM1: [64][257] @ We1 =================
    ZACC();
    mma_gemm<33>(As1, SA1, g_Bf1, acc, m0, ntb, g, tig, lane);
    // epilogue 1 -> hid
#pragma unroll
    for (int mt = 0; mt < 2; mt++) {
        int ra = m0 + mt * 16 + g, rb = ra + 8;
#pragma unroll
        for (int nt = 0; nt < 4; nt++) {
            int col = (ntb + nt) * 8 + 2 * tig;
            float b0 = s_be1[col], b1 = s_be1[col + 1];
            float2 va = make_float2(silu_f(acc[mt][nt][0] + b0), silu_f(acc[mt][nt][1] + b1));
            float2 vb = make_float2(silu_f(acc[mt][nt][2] + b0), silu_f(acc[mt][nt][3] + b1));
            *(float2*)&hid[ra * SAH + col] = va;
            *(float2*)&hid[rb * SAH + col] = vb;
        }
    }
    __syncthreads();

    // ================= GEMM2: hid @ We2 =================
    ZACC();
    mma_gemm<16>(hid, SAH, g_Bf2, acc, m0, ntb, g, tig, lane);
    // epilogue 2 -> ef (+ hagg scatter)
#pragma unroll
    for (int mt = 0; mt < 2; mt++) {
        int ra = m0 + mt * 16 + g, rb = ra + 8;
        size_t na = (size_t)s_row[ra] * 128, nb = (size_t)s_row[rb] * 128;
#pragma unroll
        for (int nt = 0; nt < 4; nt++) {
            int col = (ntb + nt) * 8 + 2 * tig;
            float b0 = s_be2[col], b1 = s_be2[col + 1];
            float v0 = silu_f(acc[mt][nt][0] + b0), v1 = silu_f(acc[mt][nt][1] + b1);
            float v2 = silu_f(acc[mt][nt][2] + b0), v3 = silu_f(acc[mt][nt][3] + b1);
            *(float2*)&ef[ra * SAH + col] = make_float2(v0, v1);
            *(float2*)&ef[rb * SAH + col] = make_float2(v2, v3);
            atomicAdd(&g_hagg[na + col], v0);
            atomicAdd(&g_hagg[na + col + 1], v1);
            atomicAdd(&g_hagg[nb + col], v2);
            atomicAdd(&g_hagg[nb + col + 1], v3);
        }
    }
    __syncthreads();

    // ================= GEMM3: ef @ Wc1 =================
    ZACC();
    mma_gemm<16>(ef, SAH, g_Bf3, acc, m0, ntb, g, tig, lane);
    // epilogue 3: partial dot with Wc2
    {
        float p[4] = {0.f, 0.f, 0.f, 0.f};
#pragma unroll
        for (int mt = 0; mt < 2; mt++) {
#pragma unroll
            for (int nt = 0; nt < 4; nt++) {
                int col = (ntb + nt) * 8 + 2 * tig;
                float b0 = s_bc1[col], b1 = s_bc1[col + 1];
                float w0 = s_wc2[col], w1 = s_wc2[col + 1];
                p[mt*2+0] += silu_f(acc[mt][nt][0] + b0) * w0
                           + silu_f(acc[mt][nt][1] + b1) * w1;
                p[mt*2+1] += silu_f(acc[mt][nt][2] + b0) * w0
                           + silu_f(acc[mt][nt][3] + b1) * w1;
            }
        }
#pragma unroll
        for (int i = 0; i < 4; i++) {
            p[i] += __shfl_xor_sync(0xffffffffu, p[i], 1);
            p[i] += __shfl_xor_sync(0xffffffffu, p[i], 2);
        }
        if (tig == 0) {
#pragma unroll
            for (int mt = 0; mt < 2; mt++) {
                s_part[nw * 64 + m0 + mt * 16 + g]     = p[mt*2+0];
                s_part[nw * 64 + m0 + mt * 16 + g + 8] = p[mt*2+1];
            }
        }
    }
    __syncthreads();

    if (tid < 64) {
        float s = s_part[tid] + s_part[64 + tid] + s_part[128 + tid] + s_part[192 + tid];
        int r = s_row[tid];
        atomicAdd(&g_cagg[r*3+0], s_diff[tid*3+0] * s);
        atomicAdd(&g_cagg[r*3+1], s_diff[tid*3+1] * s);
        atomicAdd(&g_cagg[r*3+2], s_diff[tid*3+2] * s);
        atomicAdd(&g_cnt[r], 1.0f);
    }
#undef ZACC
}

// ---------------- node kernel (scalar fp32, small) ----------------
#define NB 64
#define INS 264
#define HIS 132

template<int K, bool SILU>
__device__ __forceinline__ void gemm_tile(
    const float* __restrict__ sIn, int inStride,
    const float* __restrict__ W, const float* __restrict__ bias,
    float* __restrict__ sOut, int outStride, float* __restrict__ s_w)
{
    const int tx = threadIdx.x & 31;
    const int r0 = (threadIdx.x >> 5) * 4;
    float acc[4][4];
#pragma unroll
    for (int i = 0; i < 4; i++)
#pragma unroll
        for (int c = 0; c < 4; c++) acc[i][c] = 0.0f;

    for (int kc = 0; kc < K; kc += 16) {
        __syncthreads();
        {
            int t = threadIdx.x, r = t >> 5, c = t & 31;
            ((float4*)s_w)[r * 33 + c] = *((const float4*)(W + (size_t)(kc + r) * 128) + c);
        }
        __syncthreads();
#pragma unroll
        for (int kk = 0; kk < 16; kk += 4) {
            float4 av[4];
#pragma unroll
            for (int i = 0; i < 4; i++)
                av[i] = *(const float4*)&sIn[(r0 + i) * inStride + kc + kk];
#pragma unroll
            for (int q = 0; q < 4; q++) {
                float4 w = ((const float4*)s_w)[(kk + q) * 33 + tx];
#pragma unroll
                for (int i = 0; i < 4; i++) {
                    float a = (q == 0) ? av[i].x : (q == 1) ? av[i].y
                              : (q == 2) ? av[i].z : av[i].w;
                    acc[i][0] = fmaf(a, w.x, acc[i][0]);
                    acc[i][1] = fmaf(a, w.y, acc[i][1]);
                    acc[i][2] = fmaf(a, w.z, acc[i][2]);
                    acc[i][3] = fmaf(a, w.w, acc[i][3]);
                }
            }
        }
    }
    float4 b = *((const float4*)bias + tx);
#pragma unroll
    for (int i = 0; i < 4; i++) {
        float4 v;
        v.x = acc[i][0] + b.x; v.y = acc[i][1] + b.y;
        v.z = acc[i][2] + b.z; v.w = acc[i][3] + b.w;
        if (SILU) { v.x = silu_f(v.x); v.y = silu_f(v.y); v.z = silu_f(v.z); v.w = silu_f(v.w); }
        *(float4*)&sOut[(r0 + i) * outStride + tx * 4] = v;
    }
}

#define SMEM_NODE_BYTES ((NB*INS + 16*33*4 + NB*HIS) * 4)

__global__ void __launch_bounds__(TN, 1)
node_kernel(const float* __restrict__ h, const float* __restrict__ y,
            const float* __restrict__ Wn1, const float* __restrict__ bn1,
            const float* __restrict__ Wn2, const float* __restrict__ bn2,
            float* __restrict__ out_h, float* __restrict__ out_y)
{
    extern __shared__ float sm[];
    float* s_in  = sm;
    float* s_w   = s_in + NB * INS;
    float* s_hid = s_w + 16 * 33 * 4;

    const int tid = threadIdx.x, lane = tid & 31, wid = tid >> 5;
    const int n0 = blockIdx.x * NB;

    for (int t = wid; t < 2 * NB; t += 16) {
        int e = t >> 1, half = t & 1, n = n0 + e;
        float4 v = make_float4(0.f, 0.f, 0.f, 0.f);
        if (n < N_NODES) {
            const float* src = half ? (g_hagg + (size_t)n * 128) : (h + (size_t)n * 128);
            v = *((const float4*)src + lane);
        }
        *(float4*)&s_in[e * INS + half * 128 + lane * 4] = v;
    }

    gemm_tile<256, true>(s_in, INS, Wn1, bn1, s_hid, HIS, s_w);
    gemm_tile<128, false>(s_hid, HIS, Wn2, bn2, s_in + 128, INS, s_w);
    __syncthreads();

    for (int idx = tid; idx < NB * 128; idx += TN) {
        int e = idx >> 7, j = idx & 127, n = n0 + e;
        if (n < N_NODES)
            out_h[(size_t)n * 128 + j] = s_in[e * INS + j] + s_in[e * INS + 128 + j];
    }
    if (tid < NB) {
        int n = n0 + tid;
        if (n < N_NODES) {
            float c = g_cnt[n]; c = (c < 1.0f) ? 1.0f : c;
            out_y[n*3+0] = y[n*3+0] + g_cagg[n*3+0] / c;
            out_y[n*3+1] = y[n*3+1] + g_cagg[n*3+1] / c;
            out_y[n*3+2] = y[n*3+2] + g_cagg[n*3+2] / c;
        }
    }
}

extern "C" void kernel_launch(void* const* d_in, const int* in_sizes, int n_in,
                              void* d_out, int out_size)
{
    const float* h   = (const float*)d_in[0];
    const float* y   = (const float*)d_in[1];
    const int*   ei  = (const int*)d_in[2];
    const float* We1 = (const float*)d_in[3];
    const float* be1 = (const float*)d_in[4];
    const float* We2 = (const float*)d_in[5];
    const float* be2 = (const float*)d_in[6];
    const float* Wc1 = (const float*)d_in[7];
    const float* bc1 = (const float*)d_in[8];
    const float* Wc2 = (const float*)d_in[9];
    const float* Wn1 = (const float*)d_in[10];
    const float* bn1 = (const float*)d_in[11];
    const float* Wn2 = (const float*)d_in[12];
    const float* bn2 = (const float*)d_in[13];

    float* out_h = (float*)d_out;
    float* out_y = out_h + (size_t)N_NODES * 128;

    cudaFuncSetAttribute(edge_kernel, cudaFuncAttributeMaxDynamicSharedMemorySize,
                         SMEM_EDGE_BYTES);
    cudaFuncSetAttribute(node_kernel, cudaFuncAttributeMaxDynamicSharedMemorySize,
                         SMEM_NODE_BYTES);

    zero_kernel<<<512, TE>>>();
    prep_kernel<<<(65 * 512 + 255) / 256, 256>>>(We1, We2, Wc1);

    edge_kernel<<<N_EDGES / 64, TE, SMEM_EDGE_BYTES>>>(
        h, y, ei, be1, be2, bc1, Wc2);

    node_kernel<<<(N_NODES + NB - 1) / NB, TN, SMEM_NODE_BYTES>>>(
        h, y, Wn1, bn1, Wn2, bn2, out_h, out_y);
}

// round 6
// speedup vs baseline: 3.0263x; 1.6646x over previous
#include <cuda_runtime.h>
#include <cstdint>

#define N_NODES 10000
#define N_EDGES 640000
#define TE 256
#define TN 512

typedef uint32_t u32;

// ---------------- device scratch ----------------
__device__ float g_hagg[N_NODES * 128];
__device__ float g_cagg[N_NODES * 3];
__device__ float g_cnt[N_NODES];
// bf16 B fragments: [chunk(K=16)][ntile=16][lane=32] uint4(bh01, bh23, bl01, bl23)
__device__ uint4 g_Bf1[17 * 512];
__device__ uint4 g_Bf2[8 * 512];
__device__ uint4 g_Bf3[8 * 512];

__device__ __forceinline__ float silu_f(float x) { return x / (1.0f + __expf(-x)); }

// pack two fp32 -> bf16x2 (x0 in low half), round-to-nearest
__device__ __forceinline__ u32 bf16x2_rn(float x0, float x1) {
    u32 r; asm("cvt.rn.bf16x2.f32 %0, %1, %2;" : "=r"(r) : "f"(x1), "f"(x0)); return r;
}
// residual lo pair given hi pack
__device__ __forceinline__ u32 bf16x2_lo(float x0, float x1, u32 h) {
    float h0 = __uint_as_float(h << 16);
    float h1 = __uint_as_float(h & 0xffff0000u);
    return bf16x2_rn(x0 - h0, x1 - h1);
}

#define MMA_BF16(d, a0, a1, a2, a3, b0, b1)                                 \
    asm volatile(                                                           \
        "mma.sync.aligned.m16n8k16.row.col.f32.bf16.bf16.f32 "              \
        "{%0,%1,%2,%3},{%4,%5,%6,%7},{%8,%9},{%0,%1,%2,%3};"                \
        : "+f"((d)[0]), "+f"((d)[1]), "+f"((d)[2]), "+f"((d)[3])            \
        : "r"(a0), "r"(a1), "r"(a2), "r"(a3), "r"(b0), "r"(b1))

// ---------------- prep: weights -> bf16 hi/lo fragments ----------------
__global__ void prep_kernel(const float* __restrict__ We1,
                            const float* __restrict__ We2,
                            const float* __restrict__ Wc1)
{
    int i = blockIdx.x * blockDim.x + threadIdx.x;
    const float* W; uint4* dst; int K, idx;
    if (i < 17 * 512)       { W = We1; dst = g_Bf1; K = 257; idx = i; }
    else if (i < 25 * 512)  { W = We2; dst = g_Bf2; K = 128; idx = i - 17 * 512; }
    else if (i < 33 * 512)  { W = Wc1; dst = g_Bf3; K = 128; idx = i - 25 * 512; }
    else return;

    int c = idx >> 9, rem = idx & 511;
    int t = rem >> 5, l = rem & 31;
    int g = l >> 2, tig = l & 3;
    int n = t * 8 + g;
    int k0 = c * 16 + 2 * tig;
    float w0 = (k0     < K) ? W[(k0    ) * 128 + n] : 0.0f;
    float w1 = (k0 + 1 < K) ? W[(k0 + 1) * 128 + n] : 0.0f;
    float w2 = (k0 + 8 < K) ? W[(k0 + 8) * 128 + n] : 0.0f;
    float w3 = (k0 + 9 < K) ? W[(k0 + 9) * 128 + n] : 0.0f;
    u32 bh01 = bf16x2_rn(w0, w1), bh23 = bf16x2_rn(w2, w3);
    u32 bl01 = bf16x2_lo(w0, w1, bh01), bl23 = bf16x2_lo(w2, w3, bh23);
    dst[idx] = make_uint4(bh01, bh23, bl01, bl23);
}

__global__ void zero_kernel()
{
    int i = blockIdx.x * blockDim.x + threadIdx.x;
    int st = gridDim.x * blockDim.x;
    for (int k = i; k < N_NODES * 128; k += st) g_hagg[k] = 0.0f;
    for (int k = i; k < N_NODES * 3;   k += st) g_cagg[k] = 0.0f;
    for (int k = i; k < N_NODES;       k += st) g_cnt[k]  = 0.0f;
}

// ---------------- bf16 mma GEMM core ----------------
// Ahi/Alo: u32 bf16x2 tiles [64 rows][SA u32]; Bf: fragment array
template<int KC>
__device__ __forceinline__ void mma_gemm_bf16(
    const u32* __restrict__ Ahi, const u32* __restrict__ Alo, int SA,
    const uint4* __restrict__ Bf, float acc[2][4][4],
    int m0, int ntb, int g, int tig, int lane)
{
    const int r0 = (m0 + g) * SA + tig;
    const int r1 = r0 + 8 * SA;
    const int r2 = r0 + 16 * SA;
    const int r3 = r0 + 24 * SA;

    uint4 bf[2][4];
#pragma unroll
    for (int nt = 0; nt < 4; nt++)
        bf[0][nt] = __ldg(Bf + (ntb + nt) * 32 + lane);

#pragma unroll 2
    for (int c = 0; c < KC; c++) {
        int cur = c & 1, nxt = cur ^ 1;
        if (c + 1 < KC) {
#pragma unroll
            for (int nt = 0; nt < 4; nt++)
                bf[nxt][nt] = __ldg(Bf + ((c + 1) * 16 + ntb + nt) * 32 + lane);
        }
        int k8 = c * 8;
        u32 ah[2][4], al[2][4];
        ah[0][0] = Ahi[r0 + k8];     ah[0][1] = Ahi[r1 + k8];
        ah[0][2] = Ahi[r0 + k8 + 4]; ah[0][3] = Ahi[r1 + k8 + 4];
        ah[1][0] = Ahi[r2 + k8];     ah[1][1] = Ahi[r3 + k8];
        ah[1][2] = Ahi[r2 + k8 + 4]; ah[1][3] = Ahi[r3 + k8 + 4];
        al[0][0] = Alo[r0 + k8];     al[0][1] = Alo[r1 + k8];
        al[0][2] = Alo[r0 + k8 + 4]; al[0][3] = Alo[r1 + k8 + 4];
        al[1][0] = Alo[r2 + k8];     al[1][1] = Alo[r3 + k8];
        al[1][2] = Alo[r2 + k8 + 4]; al[1][3] = Alo[r3 + k8 + 4];
#pragma unroll
        for (int nt = 0; nt < 4; nt++) {
            u32 bh0 = bf[cur][nt].x, bh1 = bf[cur][nt].y;
            u32 bl0 = bf[cur][nt].z, bl1 = bf[cur][nt].w;
#pragma unroll
            for (int mt = 0; mt < 2; mt++) {
                MMA_BF16(acc[mt][nt], ah[mt][0], ah[mt][1], ah[mt][2], ah[mt][3], bh0, bh1);
                MMA_BF16(acc[mt][nt], al[mt][0], al[mt][1], al[mt][2], al[mt][3], bh0, bh1);
                MMA_BF16(acc[mt][nt], ah[mt][0], ah[mt][1], ah[mt][2], ah[mt][3], bl0, bl1);
            }
        }
    }
}

// ---------------- SMEM layout (u32 units) ----------------
#define SA1 140     // GEMM1 A stride: 140 = 4*35 -> conflict-free lane map
#define SH  68      // hid/ef stride: 68 = 4*17
#define OFF_AHI1 0
#define OFF_ALO1 8960
#define OFF_HIDH 17920
#define OFF_HIDL 22272
#define OFF_MISC 26624
#define SMEM_EDGE_U32 (OFF_MISC + 512 + 192 + 256 + 64 + 64)
#define SMEM_EDGE_BYTES (SMEM_EDGE_U32 * 4)

__global__ void __launch_bounds__(TE, 2)
edge_kernel(const float* __restrict__ h, const float* __restrict__ y,
            const int* __restrict__ ei,
            const float* __restrict__ be1, const float* __restrict__ be2,
            const float* __restrict__ bc1, const float* __restrict__ Wc2)
{
    extern __shared__ u32 smu[];
    u32* Ahi1 = smu + OFF_AHI1;
    u32* Alo1 = smu + OFF_ALO1;
    u32* hidH = smu + OFF_HIDH;
    u32* hidL = smu + OFF_HIDL;
    u32* efH  = smu + OFF_AHI1;          // alias over dead GEMM1 A
    u32* efL  = smu + OFF_AHI1 + 4352;
    float* s_be1  = (float*)(smu + OFF_MISC);
    float* s_be2  = s_be1 + 128;
    float* s_bc1  = s_be2 + 128;
    float* s_wc2  = s_bc1 + 128;
    float* s_diff = s_wc2 + 128;         // [64][3]
    float* s_part = s_diff + 192;        // [4][64]
    int*   s_row  = (int*)(s_part + 256);
    int*   s_col  = s_row + 64;

    const int tid  = threadIdx.x;
    const int lane = tid & 31;
    const int wid  = tid >> 5;
    const int g    = lane >> 2;
    const int tig  = lane & 3;
    const int mw   = wid >> 2;           // 0..1
    const int nw   = wid & 3;            // 0..3
    const int m0   = mw * 32;
    const int ntb  = nw * 4;
    const int e0g  = blockIdx.x * 64;

    // ---- indices, diff/radial, biases ----
    if (tid < 64) {
        int r = ei[e0g + tid], c = ei[N_EDGES + e0g + tid];
        s_row[tid] = r; s_col[tid] = c;
        float dx = y[r*3+0]-y[c*3+0], dy = y[r*3+1]-y[c*3+1], dz = y[r*3+2]-y[c*3+2];
        s_diff[tid*3+0] = dx; s_diff[tid*3+1] = dy; s_diff[tid*3+2] = dz;
        float rad = dx*dx + dy*dy + dz*dz;
        u32* rh = Ahi1 + tid * SA1;
        u32* rl = Alo1 + tid * SA1;
#pragma unroll
        for (int j = 129; j < 140; j++) { rh[j] = 0u; rl[j] = 0u; }
        u32 hr = bf16x2_rn(rad, 0.0f);
        rh[128] = hr;
        rl[128] = bf16x2_lo(rad, 0.0f, hr);
    }
    if (tid < 128) {
        s_be1[tid] = be1[tid]; s_be2[tid] = be2[tid];
        s_bc1[tid] = bc1[tid]; s_wc2[tid] = Wc2[tid];
    }
    __syncthreads();

    // ---- gather h[row]|h[col] -> bf16 hi/lo tiles ----
    for (int t = wid; t < 128; t += 8) {
        int e = t >> 1, half = t & 1;
        int node = half ? s_col[e] : s_row[e];
        float4 v = *((const float4*)(h + (size_t)node * 128) + lane);
        u32 h0 = bf16x2_rn(v.x, v.y), h1 = bf16x2_rn(v.z, v.w);
        u32 l0 = bf16x2_lo(v.x, v.y, h0), l1 = bf16x2_lo(v.z, v.w, h1);
        int o = e * SA1 + half * 64 + lane * 2;
        *(uint2*)&Ahi1[o] = make_uint2(h0, h1);
        *(uint2*)&Alo1[o] = make_uint2(l0, l1);
    }
    __syncthreads();

    float acc[2][4][4];
#define ZACC() do { _Pragma("unroll") for (int a_ = 0; a_ < 2; a_++) \
    _Pragma("unroll") for (int b_ = 0; b_ < 4; b_++) \
    _Pragma("unroll") for (int c_ = 0; c_ < 4; c_++) acc[a_][b_][c_] = 0.0f; } while (0)

    // ================= GEMM1: [64][257] @ We1 =================
    ZACC();
    mma_gemm_bf16<17>(Ahi1, Alo1, SA1, g_Bf1, acc, m0, ntb, g, tig, lane);
#pragma unroll
    for (int mt = 0; mt < 2; mt++) {
        int ra = m0 + mt * 16 + g, rb = ra + 8;
#pragma unroll
        for (int nt = 0; nt < 4; nt++) {
            int col = (ntb + nt) * 8 + 2 * tig;
            int uc  = (ntb + nt) * 4 + tig;
            float b0 = s_be1[col], b1 = s_be1[col + 1];
            float v0 = silu_f(acc[mt][nt][0] + b0), v1 = silu_f(acc[mt][nt][1] + b1);
            float v2 = silu_f(acc[mt][nt][2] + b0), v3 = silu_f(acc[mt][nt][3] + b1);
            u32 ha = bf16x2_rn(v0, v1), hb = bf16x2_rn(v2, v3);
            hidH[ra * SH + uc] = ha; hidL[ra * SH + uc] = bf16x2_lo(v0, v1, ha);
            hidH[rb * SH + uc] = hb; hidL[rb * SH + uc] = bf16x2_lo(v2, v3, hb);
        }
    }
    __syncthreads();

    // ================= GEMM2: hid @ We2 =================
    ZACC();
    mma_gemm_bf16<8>(hidH, hidL, SH, g_Bf2, acc, m0, ntb, g, tig, lane);
#pragma unroll
    for (int mt = 0; mt < 2; mt++) {
        int ra = m0 + mt * 16 + g, rb = ra + 8;
        size_t na = (size_t)s_row[ra] * 128, nb = (size_t)s_row[rb] * 128;
#pragma unroll
        for (int nt = 0; nt < 4; nt++) {
            int col = (ntb + nt) * 8 + 2 * tig;
            int uc  = (ntb + nt) * 4 + tig;
            float b0 = s_be2[col], b1 = s_be2[col + 1];
            float v0 = silu_f(acc[mt][nt][0] + b0), v1 = silu_f(acc[mt][nt][1] + b1);
            float v2 = silu_f(acc[mt][nt][2] + b0), v3 = silu_f(acc[mt][nt][3] + b1);
            u32 ha = bf16x2_rn(v0, v1), hb = bf16x2_rn(v2, v3);
            efH[ra * SH + uc] = ha; efL[ra * SH + uc] = bf16x2_lo(v0, v1, ha);
            efH[rb * SH + uc] = hb; efL[rb * SH + uc] = bf16x2_lo(v2, v3, hb);
            atomicAdd(&g_hagg[na + col],     v0);
            atomicAdd(&g_hagg[na + col + 1], v1);
            atomicAdd(&g_hagg[nb + col],     v2);
            atomicAdd(&g_hagg[nb + col + 1], v3);
        }
    }
    __syncthreads();

    // ================= GEMM3: ef @ Wc1 =================
    ZACC();
    mma_gemm_bf16<8>(efH, efL, SH, g_Bf3, acc, m0, ntb, g, tig, lane);
    {
        float p[4] = {0.f, 0.f, 0.f, 0.f};
#pragma unroll
        for (int mt = 0; mt < 2; mt++) {
#pragma unroll
            for (int nt = 0; nt < 4; nt++) {
                int col = (ntb + nt) * 8 + 2 * tig;
                float b0 = s_bc1[col], b1 = s_bc1[col + 1];
                float w0 = s_wc2[col], w1 = s_wc2[col + 1];
                p[mt*2+0] += silu_f(acc[mt][nt][0] + b0) * w0
                           + silu_f(acc[mt][nt][1] + b1) * w1;
                p[mt*2+1] += silu_f(acc[mt][nt][2] + b0) * w0
                           + silu_f(acc[mt][nt][3] + b1) * w1;
            }
        }
#pragma unroll
        for (int i = 0; i < 4; i++) {
            p[i] += __shfl_xor_sync(0xffffffffu, p[i], 1);
            p[i] += __shfl_xor_sync(0xffffffffu, p[i], 2);
        }
        if (tig == 0) {
#pragma unroll
            for (int mt = 0; mt < 2; mt++) {
                s_part[nw * 64 + m0 + mt * 16 + g]     = p[mt*2+0];
                s_part[nw * 64 + m0 + mt * 16 + g + 8] = p[mt*2+1];
            }
        }
    }
    __syncthreads();

    if (tid < 64) {
        float s = s_part[tid] + s_part[64 + tid] + s_part[128 + tid] + s_part[192 + tid];
        int r = s_row[tid];
        atomicAdd(&g_cagg[r*3+0], s_diff[tid*3+0] * s);
        atomicAdd(&g_cagg[r*3+1], s_diff[tid*3+1] * s);
        atomicAdd(&g_cagg[r*3+2], s_diff[tid*3+2] * s);
        atomicAdd(&g_cnt[r], 1.0f);
    }
#undef ZACC
}

// ---------------- node kernel (scalar fp32, small) ----------------
#define NB 64
#define INS 264
#define HIS 132

template<int K, bool SILU>
__device__ __forceinline__ void gemm_tile(
    const float* __restrict__ sIn, int inStride,
    const float* __restrict__ W, const float* __restrict__ bias,
    float* __restrict__ sOut, int outStride, float* __restrict__ s_w)
{
    const int tx = threadIdx.x & 31;
    const int r0 = (threadIdx.x >> 5) * 4;
    float acc[4][4];
#pragma unroll
    for (int i = 0; i < 4; i++)
#pragma unroll
        for (int c = 0; c < 4; c++) acc[i][c] = 0.0f;

    for (int kc = 0; kc < K; kc += 16) {
        __syncthreads();
        {
            int t = threadIdx.x, r = t >> 5, c = t & 31;
            ((float4*)s_w)[r * 33 + c] = *((const float4*)(W + (size_t)(kc + r) * 128) + c);
        }
        __syncthreads();
#pragma unroll
        for (int kk = 0; kk < 16; kk += 4) {
            float4 av[4];
#pragma unroll
            for (int i = 0; i < 4; i++)
                av[i] = *(const float4*)&sIn[(r0 + i) * inStride + kc + kk];
#pragma unroll
            for (int q = 0; q < 4; q++) {
                float4 w = ((const float4*)s_w)[(kk + q) * 33 + tx];
#pragma unroll
                for (int i = 0; i < 4; i++) {
                    float a = (q == 0) ? av[i].x : (q == 1) ? av[i].y
                              : (q == 2) ? av[i].z : av[i].w;
                    acc[i][0] = fmaf(a, w.x, acc[i][0]);
                    acc[i][1] = fmaf(a, w.y, acc[i][1]);
                    acc[i][2] = fmaf(a, w.z, acc[i][2]);
                    acc[i][3] = fmaf(a, w.w, acc[i][3]);
                }
            }
        }
    }
    float4 b = *((const float4*)bias + tx);
#pragma unroll
    for (int i = 0; i < 4; i++) {
        float4 v;
        v.x = acc[i][0] + b.x; v.y = acc[i][1] + b.y;
        v.z = acc[i][2] + b.z; v.w = acc[i][3] + b.w;
        if (SILU) { v.x = silu_f(v.x); v.y = silu_f(v.y); v.z = silu_f(v.z); v.w = silu_f(v.w); }
        *(float4*)&sOut[(r0 + i) * outStride + tx * 4] = v;
    }
}

#define SMEM_NODE_BYTES ((NB*INS + 16*33*4 + NB*HIS) * 4)

__global__ void __launch_bounds__(TN, 1)
node_kernel(const float* __restrict__ h, const float* __restrict__ y,
            const float* __restrict__ Wn1, const float* __restrict__ bn1,
            const float* __restrict__ Wn2, const float* __restrict__ bn2,
            float* __restrict__ out_h, float* __restrict__ out_y)
{
    extern __shared__ float smf[];
    float* s_in  = smf;
    float* s_w   = s_in + NB * INS;
    float* s_hid = s_w + 16 * 33 * 4;

    const int tid = threadIdx.x, lane = tid & 31, wid = tid >> 5;
    const int n0 = blockIdx.x * NB;

    for (int t = wid; t < 2 * NB; t += 16) {
        int e = t >> 1, half = t & 1, n = n0 + e;
        float4 v = make_float4(0.f, 0.f, 0.f, 0.f);
        if (n < N_NODES) {
            const float* src = half ? (g_hagg + (size_t)n * 128) : (h + (size_t)n * 128);
            v = *((const float4*)src + lane);
        }
        *(float4*)&s_in[e * INS + half * 128 + lane * 4] = v;
    }

    gemm_tile<256, true>(s_in, INS, Wn1, bn1, s_hid, HIS, s_w);
    gemm_tile<128, false>(s_hid, HIS, Wn2, bn2, s_in + 128, INS, s_w);
    __syncthreads();

    for (int idx = tid; idx < NB * 128; idx += TN) {
        int e = idx >> 7, j = idx & 127, n = n0 + e;
        if (n < N_NODES)
            out_h[(size_t)n * 128 + j] = s_in[e * INS + j] + s_in[e * INS + 128 + j];
    }
    if (tid < NB) {
        int n = n0 + tid;
        if (n < N_NODES) {
            float c = g_cnt[n]; c = (c < 1.0f) ? 1.0f : c;
            out_y[n*3+0] = y[n*3+0] + g_cagg[n*3+0] / c;
            out_y[n*3+1] = y[n*3+1] + g_cagg[n*3+1] / c;
            out_y[n*3+2] = y[n*3+2] + g_cagg[n*3+2] / c;
        }
    }
}

extern "C" void kernel_launch(void* const* d_in, const int* in_sizes, int n_in,
                              void* d_out, int out_size)
{
    const float* h   = (const float*)d_in[0];
    const float* y   = (const float*)d_in[1];
    const int*   ei  = (const int*)d_in[2];
    const float* We1 = (const float*)d_in[3];
    const float* be1 = (const float*)d_in[4];
    const float* We2 = (const float*)d_in[5];
    const float* be2 = (const float*)d_in[6];
    const float* Wc1 = (const float*)d_in[7];
    const float* bc1 = (const float*)d_in[8];
    const float* Wc2 = (const float*)d_in[9];
    const float* Wn1 = (const float*)d_in[10];
    const float* bn1 = (const float*)d_in[11];
    const float* Wn2 = (const float*)d_in[12];
    const float* bn2 = (const float*)d_in[13];

    float* out_h = (float*)d_out;
    float* out_y = out_h + (size_t)N_NODES * 128;

    cudaFuncSetAttribute(edge_kernel, cudaFuncAttributeMaxDynamicSharedMemorySize,
                         SMEM_EDGE_BYTES);
    cudaFuncSetAttribute(node_kernel, cudaFuncAttributeMaxDynamicSharedMemorySize,
                         SMEM_NODE_BYTES);

    zero_kernel<<<512, TE>>>();
    prep_kernel<<<(33 * 512 + 255) / 256, 256>>>(We1, We2, Wc1);

    edge_kernel<<<N_EDGES / 64, TE, SMEM_EDGE_BYTES>>>(
        h, y, ei, be1, be2, bc1, Wc2);

    node_kernel<<<(N_NODES + NB - 1) / NB, TN, SMEM_NODE_BYTES>>>(
        h, y, Wn1, bn1, Wn2, bn2, out_h, out_y);
}

// round 7
// speedup vs baseline: 4.3677x; 1.4433x over previous
#include <cuda_runtime.h>
#include <cstdint>

#define N_NODES 10000
#define N_EDGES 640000
#define TE 256
#define TN 512

typedef uint32_t u32;

// ---------------- device scratch ----------------
__device__ float g_hagg[N_NODES * 128];
__device__ float g_cagg[N_NODES * 3];
__device__ float g_cnt[N_NODES];
__device__ float g_P[N_NODES * 128];   // h @ We1[0:128] + be1
__device__ float g_Q[N_NODES * 128];   // h @ We1[128:256]
__device__ float g_zb[128];            // stays zero (module zero-init)
// bf16 B fragments: [chunk(K=16)][ntile=16][lane=32]
__device__ uint4 g_Bf2[8 * 512];       // (bh01, bh23, bl01, bl23)
__device__ uint2 g_Bf3[8 * 512];       // (bh01, bh23) hi-only

__device__ __forceinline__ float silu_f(float x) { return x / (1.0f + __expf(-x)); }

__device__ __forceinline__ u32 bf16x2_rn(float x0, float x1) {
    u32 r; asm("cvt.rn.bf16x2.f32 %0, %1, %2;" : "=r"(r) : "f"(x1), "f"(x0)); return r;
}
__device__ __forceinline__ u32 bf16x2_lo(float x0, float x1, u32 h) {
    float h0 = __uint_as_float(h << 16);
    float h1 = __uint_as_float(h & 0xffff0000u);
    return bf16x2_rn(x0 - h0, x1 - h1);
}

#define MMA_BF16(d, a0, a1, a2, a3, b0, b1)                                 \
    asm volatile(                                                           \
        "mma.sync.aligned.m16n8k16.row.col.f32.bf16.bf16.f32 "              \
        "{%0,%1,%2,%3},{%4,%5,%6,%7},{%8,%9},{%0,%1,%2,%3};"                \
        : "+f"((d)[0]), "+f"((d)[1]), "+f"((d)[2]), "+f"((d)[3])            \
        : "r"(a0), "r"(a1), "r"(a2), "r"(a3), "r"(b0), "r"(b1))

// ---------------- prep: We2/Wc1 -> bf16 fragments ----------------
__global__ void prep_kernel(const float* __restrict__ We2,
                            const float* __restrict__ Wc1)
{
    int i = blockIdx.x * blockDim.x + threadIdx.x;
    if (i >= 8192) return;
    const float* W = (i < 4096) ? We2 : Wc1;
    int idx = i & 4095;
    int c = idx >> 9, rem = idx & 511;
    int t = rem >> 5, l = rem & 31;
    int g = l >> 2, tig = l & 3;
    int n = t * 8 + g;
    int k0 = c * 16 + 2 * tig;
    float w0 = W[(k0    ) * 128 + n];
    float w1 = W[(k0 + 1) * 128 + n];
    float w2 = W[(k0 + 8) * 128 + n];
    float w3 = W[(k0 + 9) * 128 + n];
    u32 bh01 = bf16x2_rn(w0, w1), bh23 = bf16x2_rn(w2, w3);
    if (i < 4096) {
        g_Bf2[idx] = make_uint4(bh01, bh23,
                                bf16x2_lo(w0, w1, bh01), bf16x2_lo(w2, w3, bh23));
    } else {
        g_Bf3[idx] = make_uint2(bh01, bh23);
    }
}

__global__ void zero_kernel()
{
    int i = blockIdx.x * blockDim.x + threadIdx.x;
    int st = gridDim.x * blockDim.x;
    for (int k = i; k < N_NODES * 128; k += st) g_hagg[k] = 0.0f;
    for (int k = i; k < N_NODES * 3;   k += st) g_cagg[k] = 0.0f;
    for (int k = i; k < N_NODES;       k += st) g_cnt[k]  = 0.0f;
}

// ---------------- scalar fp32 GEMM tile (512 threads, 64 rows) ----------------
template<int K, bool SILU>
__device__ __forceinline__ void gemm_tile(
    const float* __restrict__ sIn, int inStride,
    const float* __restrict__ W, const float* __restrict__ bias,
    float* __restrict__ sOut, int outStride, float* __restrict__ s_w)
{
    const int tx = threadIdx.x & 31;
    const int r0 = (threadIdx.x >> 5) * 4;
    float acc[4][4];
#pragma unroll
    for (int i = 0; i < 4; i++)
#pragma unroll
        for (int c = 0; c < 4; c++) acc[i][c] = 0.0f;

    for (int kc = 0; kc < K; kc += 16) {
        __syncthreads();
        {
            int t = threadIdx.x, r = t >> 5, c = t & 31;
            ((float4*)s_w)[r * 33 + c] = *((const float4*)(W + (size_t)(kc + r) * 128) + c);
        }
        __syncthreads();
#pragma unroll
        for (int kk = 0; kk < 16; kk += 4) {
            float4 av[4];
#pragma unroll
            for (int i = 0; i < 4; i++)
                av[i] = *(const float4*)&sIn[(r0 + i) * inStride + kc + kk];
#pragma unroll
            for (int q = 0; q < 4; q++) {
                float4 w = ((const float4*)s_w)[(kk + q) * 33 + tx];
#pragma unroll
                for (int i = 0; i < 4; i++) {
                    float a = (q == 0) ? av[i].x : (q == 1) ? av[i].y
                              : (q == 2) ? av[i].z : av[i].w;
                    acc[i][0] = fmaf(a, w.x, acc[i][0]);
                    acc[i][1] = fmaf(a, w.y, acc[i][1]);
                    acc[i][2] = fmaf(a, w.z, acc[i][2]);
                    acc[i][3] = fmaf(a, w.w, acc[i][3]);
                }
            }
        }
    }
    float4 b = *((const float4*)bias + tx);
#pragma unroll
    for (int i = 0; i < 4; i++) {
        float4 v;
        v.x = acc[i][0] + b.x; v.y = acc[i][1] + b.y;
        v.z = acc[i][2] + b.z; v.w = acc[i][3] + b.w;
        if (SILU) { v.x = silu_f(v.x); v.y = silu_f(v.y); v.z = silu_f(v.z); v.w = silu_f(v.w); }
        *(float4*)&sOut[(r0 + i) * outStride + tx * 4] = v;
    }
}

// ---------------- pre: P = h@We1_top + be1, Q = h@We1_bot ----------------
#define PRE_SMEM_BYTES ((64*132 + 16*33*4 + 64*132) * 4)
__global__ void __launch_bounds__(TN, 1)
pre_kernel(const float* __restrict__ h, const float* __restrict__ We1,
           const float* __restrict__ be1)
{
    extern __shared__ float smf[];
    float* s_in  = smf;
    float* s_w   = s_in + 64 * 132;
    float* s_out = s_w + 16 * 33 * 4;
    const int tid = threadIdx.x;
    const int n0  = blockIdx.x * 64;

    for (int idx = tid; idx < 64 * 128; idx += TN) {
        int r = idx >> 7, c = idx & 127, n = n0 + r;
        s_in[r * 132 + c] = (n < N_NODES) ? h[(size_t)n * 128 + c] : 0.0f;
    }
    gemm_tile<128, false>(s_in, 132, We1, be1, s_out, 132, s_w);
    __syncthreads();
    for (int idx = tid; idx < 64 * 128; idx += TN) {
        int r = idx >> 7, c = idx & 127, n = n0 + r;
        if (n < N_NODES) g_P[(size_t)n * 128 + c] = s_out[r * 132 + c];
    }
    __syncthreads();
    gemm_tile<128, false>(s_in, 132, We1 + 128 * 128, g_zb, s_out, 132, s_w);
    __syncthreads();
    for (int idx = tid; idx < 64 * 128; idx += TN) {
        int r = idx >> 7, c = idx & 127, n = n0 + r;
        if (n < N_NODES) g_Q[(size_t)n * 128 + c] = s_out[r * 132 + c];
    }
}

// ---------------- bf16 mma cores ----------------
template<int KC>
__device__ __forceinline__ void mma_gemm_bf16(
    const u32* __restrict__ Ahi, const u32* __restrict__ Alo, int SA,
    const uint4* __restrict__ Bf, float acc[2][4][4],
    int m0, int ntb, int g, int tig, int lane)
{
    const int r0 = (m0 + g) * SA + tig;
    const int r1 = r0 + 8 * SA;
    const int r2 = r0 + 16 * SA;
    const int r3 = r0 + 24 * SA;

    uint4 bf[2][4];
#pragma unroll
    for (int nt = 0; nt < 4; nt++)
        bf[0][nt] = __ldg(Bf + (ntb + nt) * 32 + lane);

#pragma unroll 2
    for (int c = 0; c < KC; c++) {
        int cur = c & 1, nxt = cur ^ 1;
        if (c + 1 < KC) {
#pragma unroll
            for (int nt = 0; nt < 4; nt++)
                bf[nxt][nt] = __ldg(Bf + ((c + 1) * 16 + ntb + nt) * 32 + lane);
        }
        int k8 = c * 8;
        u32 ah[2][4], al[2][4];
        ah[0][0] = Ahi[r0 + k8];     ah[0][1] = Ahi[r1 + k8];
        ah[0][2] = Ahi[r0 + k8 + 4]; ah[0][3] = Ahi[r1 + k8 + 4];
        ah[1][0] = Ahi[r2 + k8];     ah[1][1] = Ahi[r3 + k8];
        ah[1][2] = Ahi[r2 + k8 + 4]; ah[1][3] = Ahi[r3 + k8 + 4];
        al[0][0] = Alo[r0 + k8];     al[0][1] = Alo[r1 + k8];
        al[0][2] = Alo[r0 + k8 + 4]; al[0][3] = Alo[r1 + k8 + 4];
        al[1][0] = Alo[r2 + k8];     al[1][1] = Alo[r3 + k8];
        al[1][2] = Alo[r2 + k8 + 4]; al[1][3] = Alo[r3 + k8 + 4];
#pragma unroll
        for (int nt = 0; nt < 4; nt++) {
            u32 bh0 = bf[cur][nt].x, bh1 = bf[cur][nt].y;
            u32 bl0 = bf[cur][nt].z, bl1 = bf[cur][nt].w;
#pragma unroll
            for (int mt = 0; mt < 2; mt++) {
                MMA_BF16(acc[mt][nt], ah[mt][0], ah[mt][1], ah[mt][2], ah[mt][3], bh0, bh1);
                MMA_BF16(acc[mt][nt], al[mt][0], al[mt][1], al[mt][2], al[mt][3], bh0, bh1);
                MMA_BF16(acc[mt][nt], ah[mt][0], ah[mt][1], ah[mt][2], ah[mt][3], bl0, bl1);
            }
        }
    }
}

// 2-term variant (A hi+lo vs B hi only), uint2 fragments
template<int KC>
__device__ __forceinline__ void mma_gemm_bf16_2t(
    const u32* __restrict__ Ahi, const u32* __restrict__ Alo, int SA,
    const uint2* __restrict__ Bf, float acc[2][4][4],
    int m0, int ntb, int g, int tig, int lane)
{
    const int r0 = (m0 + g) * SA + tig;
    const int r1 = r0 + 8 * SA;
    const int r2 = r0 + 16 * SA;
    const int r3 = r0 + 24 * SA;

    uint2 bf[2][4];
#pragma unroll
    for (int nt = 0; nt < 4; nt++)
        bf[0][nt] = __ldg(Bf + (ntb + nt) * 32 + lane);

#pragma unroll 2
    for (int c = 0; c < KC; c++) {
        int cur = c & 1, nxt = cur ^ 1;
        if (c + 1 < KC) {
#pragma unroll
            for (int nt = 0; nt < 4; nt++)
                bf[nxt][nt] = __ldg(Bf + ((c + 1) * 16 + ntb + nt) * 32 + lane);
        }
        int k8 = c * 8;
        u32 ah[2][4], al[2][4];
        ah[0][0] = Ahi[r0 + k8];     ah[0][1] = Ahi[r1 + k8];
        ah[0][2] = Ahi[r0 + k8 + 4]; ah[0][3] = Ahi[r1 + k8 + 4];
        ah[1][0] = Ahi[r2 + k8];     ah[1][1] = Ahi[r3 + k8];
        ah[1][2] = Ahi[r2 + k8 + 4]; ah[1][3] = Ahi[r3 + k8 + 4];
        al[0][0] = Alo[r0 + k8];     al[0][1] = Alo[r1 + k8];
        al[0][2] = Alo[r0 + k8 + 4]; al[0][3] = Alo[r1 + k8 + 4];
        al[1][0] = Alo[r2 + k8];     al[1][1] = Alo[r3 + k8];
        al[1][2] = Alo[r2 + k8 + 4]; al[1][3] = Alo[r3 + k8 + 4];
#pragma unroll
        for (int nt = 0; nt < 4; nt++) {
            u32 bh0 = bf[cur][nt].x, bh1 = bf[cur][nt].y;
#pragma unroll
            for (int mt = 0; mt < 2; mt++) {
                MMA_BF16(acc[mt][nt], ah[mt][0], ah[mt][1], ah[mt][2], ah[mt][3], bh0, bh1);
                MMA_BF16(acc[mt][nt], al[mt][0], al[mt][1], al[mt][2], al[mt][3], bh0, bh1);
            }
        }
    }
}

// ---------------- SMEM layout (u32 units) ----------------
#define SH 68
#define OFF_HIDH 0
#define OFF_HIDL 4352
#define OFF_EFH  8704
#define OFF_EFL  13056
#define OFF_MISC 17408
#define SMEM_EDGE_U32 (OFF_MISC + 1152)
#define SMEM_EDGE_BYTES (SMEM_EDGE_U32 * 4)

__global__ void __launch_bounds__(TE, 2)
edge_kernel(const float* __restrict__ y, const int* __restrict__ ei,
            const float* __restrict__ w256,   // = We1 + 256*128
            const float* __restrict__ be2, const float* __restrict__ bc1,
            const float* __restrict__ Wc2)
{
    extern __shared__ u32 smu[];
    u32* hidH = smu + OFF_HIDH;
    u32* hidL = smu + OFF_HIDL;
    u32* efH  = smu + OFF_EFH;
    u32* efL  = smu + OFF_EFL;
    float* s_w256 = (float*)(smu + OFF_MISC);
    float* s_be2  = s_w256 + 128;
    float* s_bc1  = s_be2 + 128;
    float* s_wc2  = s_bc1 + 128;
    float* s_rad  = s_wc2 + 128;          // [64]
    float* s_diff = s_rad + 64;           // [64][3]
    float* s_part = s_diff + 192;         // [4][64]
    int*   s_row  = (int*)(s_part + 256); // [64]
    int*   s_col  = s_row + 64;           // [64]

    const int tid  = threadIdx.x;
    const int lane = tid & 31;
    const int wid  = tid >> 5;
    const int g    = lane >> 2;
    const int tig  = lane & 3;
    const int mw   = wid >> 2;            // 0..1
    const int nw   = wid & 3;             // 0..3
    const int m0   = mw * 32;
    const int ntb  = nw * 4;
    const int e0g  = blockIdx.x * 64;

    if (tid < 64) {
        int r = ei[e0g + tid], c = ei[N_EDGES + e0g + tid];
        s_row[tid] = r; s_col[tid] = c;
        float dx = y[r*3+0]-y[c*3+0], dy = y[r*3+1]-y[c*3+1], dz = y[r*3+2]-y[c*3+2];
        s_diff[tid*3+0] = dx; s_diff[tid*3+1] = dy; s_diff[tid*3+2] = dz;
        s_rad[tid] = dx*dx + dy*dy + dz*dz;
    }
    if (tid < 128) {
        s_w256[tid] = w256[tid];
        s_be2[tid] = be2[tid]; s_bc1[tid] = bc1[tid]; s_wc2[tid] = Wc2[tid];
    }
    __syncthreads();

    // ---- fused former-GEMM1: hid = silu(P[row] + Q[col] + rad*w256) ----
#pragma unroll 2
    for (int t = wid; t < 64; t += 8) {
        int rnode = s_row[t], cnode = s_col[t];
        float4 p = __ldg((const float4*)(g_P + (size_t)rnode * 128) + lane);
        float4 q = __ldg((const float4*)(g_Q + (size_t)cnode * 128) + lane);
        float rad = s_rad[t];
        float4 w = *(const float4*)&s_w256[lane * 4];
        float v0 = silu_f(p.x + q.x + rad * w.x);
        float v1 = silu_f(p.y + q.y + rad * w.y);
        float v2 = silu_f(p.z + q.z + rad * w.z);
        float v3 = silu_f(p.w + q.w + rad * w.w);
        u32 h0 = bf16x2_rn(v0, v1), h1 = bf16x2_rn(v2, v3);
        int o = t * SH + lane * 2;
        *(uint2*)&hidH[o] = make_uint2(h0, h1);
        *(uint2*)&hidL[o] = make_uint2(bf16x2_lo(v0, v1, h0), bf16x2_lo(v2, v3, h1));
    }
    __syncthreads();

    float acc[2][4][4];
#define ZACC() do { _Pragma("unroll") for (int a_ = 0; a_ < 2; a_++) \
    _Pragma("unroll") for (int b_ = 0; b_ < 4; b_++) \
    _Pragma("unroll") for (int c_ = 0; c_ < 4; c_++) acc[a_][b_][c_] = 0.0f; } while (0)

    // ================= GEMM2: hid @ We2 (3-term) =================
    ZACC();
    mma_gemm_bf16<8>(hidH, hidL, SH, g_Bf2, acc, m0, ntb, g, tig, lane);
#pragma unroll
    for (int mt = 0; mt < 2; mt++) {
        int ra = m0 + mt * 16 + g, rb = ra + 8;
        size_t na = (size_t)s_row[ra] * 128, nb = (size_t)s_row[rb] * 128;
#pragma unroll
        for (int nt = 0; nt < 4; nt++) {
            int col = (ntb + nt) * 8 + 2 * tig;
            int uc  = (ntb + nt) * 4 + tig;
            float b0 = s_be2[col], b1 = s_be2[col + 1];
            float v0 = silu_f(acc[mt][nt][0] + b0), v1 = silu_f(acc[mt][nt][1] + b1);
            float v2 = silu_f(acc[mt][nt][2] + b0), v3 = silu_f(acc[mt][nt][3] + b1);
            u32 ha = bf16x2_rn(v0, v1), hb = bf16x2_rn(v2, v3);
            efH[ra * SH + uc] = ha; efL[ra * SH + uc] = bf16x2_lo(v0, v1, ha);
            efH[rb * SH + uc] = hb; efL[rb * SH + uc] = bf16x2_lo(v2, v3, hb);
            atomicAdd(&g_hagg[na + col],     v0);
            atomicAdd(&g_hagg[na + col + 1], v1);
            atomicAdd(&g_hagg[nb + col],     v2);
            atomicAdd(&g_hagg[nb + col + 1], v3);
        }
    }
    __syncthreads();

    // ================= GEMM3: ef @ Wc1 (2-term) =================
    ZACC();
    mma_gemm_bf16_2t<8>(efH, efL, SH, g_Bf3, acc, m0, ntb, g, tig, lane);
    {
        float p[4] = {0.f, 0.f, 0.f, 0.f};
#pragma unroll
        for (int mt = 0; mt < 2; mt++) {
#pragma unroll
            for (int nt = 0; nt < 4; nt++) {
                int col = (ntb + nt) * 8 + 2 * tig;
                float b0 = s_bc1[col], b1 = s_bc1[col + 1];
                float w0 = s_wc2[col], w1 = s_wc2[col + 1];
                p[mt*2+0] += silu_f(acc[mt][nt][0] + b0) * w0
                           + silu_f(acc[mt][nt][1] + b1) * w1;
                p[mt*2+1] += silu_f(acc[mt][nt][2] + b0) * w0
                           + silu_f(acc[mt][nt][3] + b1) * w1;
            }
        }
#pragma unroll
        for (int i = 0; i < 4; i++) {
            p[i] += __shfl_xor_sync(0xffffffffu, p[i], 1);
            p[i] += __shfl_xor_sync(0xffffffffu, p[i], 2);
        }
        if (tig == 0) {
#pragma unroll
            for (int mt = 0; mt < 2; mt++) {
                s_part[nw * 64 + m0 + mt * 16 + g]     = p[mt*2+0];
                s_part[nw * 64 + m0 + mt * 16 + g + 8] = p[mt*2+1];
            }
        }
    }
    __syncthreads();

    if (tid < 64) {
        float s = s_part[tid] + s_part[64 + tid] + s_part[128 + tid] + s_part[192 + tid];
        int r = s_row[tid];
        atomicAdd(&g_cagg[r*3+0], s_diff[tid*3+0] * s);
        atomicAdd(&g_cagg[r*3+1], s_diff[tid*3+1] * s);
        atomicAdd(&g_cagg[r*3+2], s_diff[tid*3+2] * s);
        atomicAdd(&g_cnt[r], 1.0f);
    }
#undef ZACC
}

// ---------------- node kernel (unchanged) ----------------
#define NB 64
#define INS 264
#define HIS 132
#define SMEM_NODE_BYTES ((NB*INS + 16*33*4 + NB*HIS) * 4)

__global__ void __launch_bounds__(TN, 1)
node_kernel(const float* __restrict__ h, const float* __restrict__ y,
            const float* __restrict__ Wn1, const float* __restrict__ bn1,
            const float* __restrict__ Wn2, const float* __restrict__ bn2,
            float* __restrict__ out_h, float* __restrict__ out_y)
{
    extern __shared__ float smf[];
    float* s_in  = smf;
    float* s_w   = s_in + NB * INS;
    float* s_hid = s_w + 16 * 33 * 4;

    const int tid = threadIdx.x, lane = tid & 31, wid = tid >> 5;
    const int n0 = blockIdx.x * NB;

    for (int t = wid; t < 2 * NB; t += 16) {
        int e = t >> 1, half = t & 1, n = n0 + e;
        float4 v = make_float4(0.f, 0.f, 0.f, 0.f);
        if (n < N_NODES) {
            const float* src = half ? (g_hagg + (size_t)n * 128) : (h + (size_t)n * 128);
            v = *((const float4*)src + lane);
        }
        *(float4*)&s_in[e * INS + half * 128 + lane * 4] = v;
    }

    gemm_tile<256, true>(s_in, INS, Wn1, bn1, s_hid, HIS, s_w);
    gemm_tile<128, false>(s_hid, HIS, Wn2, bn2, s_in + 128, INS, s_w);
    __syncthreads();

    for (int idx = tid; idx < NB * 128; idx += TN) {
        int e = idx >> 7, j = idx & 127, n = n0 + e;
        if (n < N_NODES)
            out_h[(size_t)n * 128 + j] = s_in[e * INS + j] + s_in[e * INS + 128 + j];
    }
    if (tid < NB) {
        int n = n0 + tid;
        if (n < N_NODES) {
            float c = g_cnt[n]; c = (c < 1.0f) ? 1.0f : c;
            out_y[n*3+0] = y[n*3+0] + g_cagg[n*3+0] / c;
            out_y[n*3+1] = y[n*3+1] + g_cagg[n*3+1] / c;
            out_y[n*3+2] = y[n*3+2] + g_cagg[n*3+2] / c;
        }
    }
}

extern "C" void kernel_launch(void* const* d_in, const int* in_sizes, int n_in,
                              void* d_out, int out_size)
{
    const float* h   = (const float*)d_in[0];
    const float* y   = (const float*)d_in[1];
    const int*   ei  = (const int*)d_in[2];
    const float* We1 = (const float*)d_in[3];
    const float* be1 = (const float*)d_in[4];
    const float* We2 = (const float*)d_in[5];
    const float* be2 = (const float*)d_in[6];
    const float* Wc1 = (const float*)d_in[7];
    const float* bc1 = (const float*)d_in[8];
    const float* Wc2 = (const float*)d_in[9];
    const float* Wn1 = (const float*)d_in[10];
    const float* bn1 = (const float*)d_in[11];
    const float* Wn2 = (const float*)d_in[12];
    const float* bn2 = (const float*)d_in[13];

    float* out_h = (float*)d_out;
    float* out_y = out_h + (size_t)N_NODES * 128;

    cudaFuncSetAttribute(edge_kernel, cudaFuncAttributeMaxDynamicSharedMemorySize,
                         SMEM_EDGE_BYTES);
    cudaFuncSetAttribute(node_kernel, cudaFuncAttributeMaxDynamicSharedMemorySize,
                         SMEM_NODE_BYTES);
    cudaFuncSetAttribute(pre_kernel, cudaFuncAttributeMaxDynamicSharedMemorySize,
                         PRE_SMEM_BYTES);

    zero_kernel<<<512, TE>>>();
    prep_kernel<<<32, 256>>>(We2, Wc1);
    pre_kernel<<<(N_NODES + 63) / 64, TN, PRE_SMEM_BYTES>>>(h, We1, be1);

    edge_kernel<<<N_EDGES / 64, TE, SMEM_EDGE_BYTES>>>(
        y, ei, We1 + 256 * 128, be2, bc1, Wc2);

    node_kernel<<<(N_NODES + NB - 1) / NB, TN, SMEM_NODE_BYTES>>>(
        h, y, Wn1, bn1, Wn2, bn2, out_h, out_y);
}